// round 3
// baseline (speedup 1.0000x reference)
#include <cuda_runtime.h>

// GCNConv_74131135529465: 3x [BatchNorm -> GraphConv(norm=both) -> ReLU]
// N=10000 nodes, E=160000 edges, D=512, L=3.
//
// Pipeline per launch (all graph-capturable, no allocs):
//  0. detect src/dst dtype (int32 vs int64) on-device; convert to int32 with clamp
//  1. zero counters; compute in/out degrees; norms = rsqrt(max(deg,1))
//  2. block-parallel prefix sum of in-degree -> CSR row offsets; scatter edges
//  per layer:
//  3. BN stats (col sum/sumsq) -> scale/shift; fused normalize * src_norm -> h
//  4. CSR gather-sum per dst node * dst_norm -> agg   (h fits in L2, no atomics)
//  5. fp32 tiled SGEMM 128x128x16 + bias + ReLU -> next x (or d_out)

#define D 512
#define D4 128           // D / 4 (float4)
#define NMAX 10240
#define EMAX 200000

__device__ float g_h[(size_t)NMAX * D];
__device__ float g_agg[(size_t)NMAX * D];
__device__ float g_x[(size_t)NMAX * D];
__device__ float g_srcnorm[NMAX];
__device__ float g_dstnorm[NMAX];
__device__ int   g_src[EMAX];
__device__ int   g_dst[EMAX];
__device__ int   g_outdeg[NMAX];
__device__ int   g_indeg[NMAX];
__device__ int   g_cursor[NMAX];
__device__ int   g_rowoff[NMAX + 1];
__device__ int   g_csr[EMAX];
__device__ float g_colsum[D];
__device__ float g_colsq[D];
__device__ float g_scale[D];
__device__ float g_shift[D];
__device__ int   g_is64;

// ------------------------------------------------------------ dtype handling

// If the buffer holds little-endian int64 values < 2^32, every odd int32 word
// (high half) is 0. For genuine int32 node indices in [0, N), 64 consecutive
// zeros is impossible in practice.
__global__ void detect_dtype_kernel(const int* __restrict__ p) {
    if (threadIdx.x == 0) {
        int all0 = 1;
        for (int i = 1; i < 128; i += 2)
            if (p[i] != 0) { all0 = 0; break; }
        g_is64 = all0;
    }
}

__global__ void convert_idx_kernel(const void* __restrict__ srcp,
                                   const void* __restrict__ dstp,
                                   int E, int N) {
    int e = blockIdx.x * blockDim.x + threadIdx.x;
    if (e >= E) return;
    int s, d;
    if (g_is64) {
        s = (int)((const long long*)srcp)[e];
        d = (int)((const long long*)dstp)[e];
    } else {
        s = ((const int*)srcp)[e];
        d = ((const int*)dstp)[e];
    }
    // defensive clamp: a wild index must never become a wild pointer
    s = min(max(s, 0), N - 1);
    d = min(max(d, 0), N - 1);
    g_src[e] = s;
    g_dst[e] = d;
}

// ---------------------------------------------------------------- graph prep

__global__ void init_counts_kernel(int N) {
    int i = blockIdx.x * blockDim.x + threadIdx.x;
    if (i < N) {
        g_outdeg[i] = 0;
        g_indeg[i]  = 0;
        g_cursor[i] = 0;
    }
}

__global__ void degree_kernel(int E) {
    int e = blockIdx.x * blockDim.x + threadIdx.x;
    if (e < E) {
        atomicAdd(&g_outdeg[g_src[e]], 1);
        atomicAdd(&g_indeg[g_dst[e]], 1);
    }
}

__global__ void norm_kernel(int N) {
    int i = blockIdx.x * blockDim.x + threadIdx.x;
    if (i < N) {
        int od = g_outdeg[i]; if (od < 1) od = 1;
        int id = g_indeg[i];  if (id < 1) id = 1;
        g_srcnorm[i] = rsqrtf((float)od);
        g_dstnorm[i] = rsqrtf((float)id);
    }
}

// Single-block (1024 threads) exclusive prefix sum of in-degree -> row offsets.
__global__ void scan_kernel(int N) {
    __shared__ int warp_sums[32];
    int tid  = threadIdx.x;
    int lane = tid & 31;
    int wid  = tid >> 5;
    int chunk = (N + 1023) / 1024;
    int start = tid * chunk;
    int end   = start + chunk; if (end > N) end = N;

    int s = 0;
    for (int i = start; i < end; i++) s += g_indeg[i];

    int v = s;
    #pragma unroll
    for (int o = 1; o < 32; o <<= 1) {
        int t = __shfl_up_sync(0xFFFFFFFFu, v, o);
        if (lane >= o) v += t;
    }
    if (lane == 31) warp_sums[wid] = v;
    __syncthreads();
    if (wid == 0) {
        int w = warp_sums[lane];
        #pragma unroll
        for (int o = 1; o < 32; o <<= 1) {
            int t = __shfl_up_sync(0xFFFFFFFFu, w, o);
            if (lane >= o) w += t;
        }
        warp_sums[lane] = w;
    }
    __syncthreads();

    int excl = (v - s) + (wid > 0 ? warp_sums[wid - 1] : 0);
    int run = excl;
    for (int i = start; i < end; i++) {
        g_rowoff[i] = run;
        run += g_indeg[i];
    }
    if (start < N && end == N) g_rowoff[N] = run;
}

__global__ void csr_fill_kernel(int E) {
    int e = blockIdx.x * blockDim.x + threadIdx.x;
    if (e < E) {
        int d = g_dst[e];
        int p = atomicAdd(&g_cursor[d], 1);
        g_csr[g_rowoff[d] + p] = g_src[e];
    }
}

// ---------------------------------------------------------------- batch norm

__global__ void bn_zero_kernel() {
    int j = threadIdx.x;
    g_colsum[j] = 0.f;
    g_colsq[j]  = 0.f;
}

// x_ext == nullptr -> read from g_x
__global__ void bn_stats_kernel(const float* __restrict__ x_ext, int N) {
    const float* __restrict__ x = x_ext ? x_ext : g_x;
    int t = threadIdx.x;            // 256 threads: columns t and t+256
    float s0 = 0.f, q0 = 0.f, s1 = 0.f, q1 = 0.f;
    for (int r = blockIdx.x; r < N; r += gridDim.x) {
        float v0 = x[(size_t)r * D + t];
        float v1 = x[(size_t)r * D + t + 256];
        s0 += v0; q0 += v0 * v0;
        s1 += v1; q1 += v1 * v1;
    }
    atomicAdd(&g_colsum[t],       s0);
    atomicAdd(&g_colsq[t],        q0);
    atomicAdd(&g_colsum[t + 256], s1);
    atomicAdd(&g_colsq[t + 256],  q1);
}

__global__ void bn_final_kernel(const float* __restrict__ gamma,
                                const float* __restrict__ beta, float invN) {
    int j = threadIdx.x;  // 512
    float mu  = g_colsum[j] * invN;
    float var = g_colsq[j] * invN - mu * mu;
    float rs  = rsqrtf(var + 1e-5f);
    float sc  = rs * gamma[j];
    g_scale[j] = sc;
    g_shift[j] = beta[j] - mu * sc;
}

// h[i,j] = ((x[i,j]-mu)*rsig*gamma + beta) * src_norm[i]  (folded scale/shift)
__global__ void normscale_kernel(const float* __restrict__ x_ext, int N) {
    const float* __restrict__ x = x_ext ? x_ext : g_x;
    int i4 = blockIdx.x * blockDim.x + threadIdx.x;   // over N * D4
    if (i4 >= N * D4) return;
    int c4  = i4 & (D4 - 1);
    int row = i4 >> 7;
    float4 v  = ((const float4*)x)[i4];
    float4 sc = ((const float4*)g_scale)[c4];
    float4 sh = ((const float4*)g_shift)[c4];
    float sn  = g_srcnorm[row];
    float4 o;
    o.x = (v.x * sc.x + sh.x) * sn;
    o.y = (v.y * sc.y + sh.y) * sn;
    o.z = (v.z * sc.z + sh.z) * sn;
    o.w = (v.w * sc.w + sh.w) * sn;
    ((float4*)g_h)[i4] = o;
}

// ---------------------------------------------------------------- aggregation

__global__ void aggregate_kernel(int N) {
    int node = blockIdx.x;
    int t = threadIdx.x;                 // 128 threads, float4 each = 512 cols
    int e0 = g_rowoff[node], e1 = g_rowoff[node + 1];
    const float4* __restrict__ h4 = (const float4*)g_h;
    float4 acc = make_float4(0.f, 0.f, 0.f, 0.f);
    int e = e0;
    for (; e + 1 < e1; e += 2) {
        int s0 = g_csr[e], s1 = g_csr[e + 1];
        float4 v0 = h4[(size_t)s0 * D4 + t];
        float4 v1 = h4[(size_t)s1 * D4 + t];
        acc.x += v0.x + v1.x;
        acc.y += v0.y + v1.y;
        acc.z += v0.z + v1.z;
        acc.w += v0.w + v1.w;
    }
    if (e < e1) {
        int s = g_csr[e];
        float4 v = h4[(size_t)s * D4 + t];
        acc.x += v.x; acc.y += v.y; acc.z += v.z; acc.w += v.w;
    }
    float dn = g_dstnorm[node];
    float4 o = make_float4(acc.x * dn, acc.y * dn, acc.z * dn, acc.w * dn);
    ((float4*)g_agg)[(size_t)node * D4 + t] = o;
}

// ---------------------------------------------------------------- SGEMM

// C = relu(g_agg @ B + bias), C = Cext (if non-null) else g_x.
// 128x128 tile, BK=16, 256 threads, 8x8 per thread.
__global__ __launch_bounds__(256, 1)
void gemm_bias_relu_kernel(const float* __restrict__ B,
                           const float* __restrict__ bias,
                           float* __restrict__ Cext, int M) {
    const float* __restrict__ A = g_agg;
    float* __restrict__ C = Cext ? Cext : g_x;
    __shared__ float As[16][128];
    __shared__ float Bs[16][128];
    int bm = blockIdx.x * 128;
    int bn = blockIdx.y * 128;
    int tid = threadIdx.x;
    int tx = tid & 15, ty = tid >> 4;

    float acc[8][8];
    #pragma unroll
    for (int i = 0; i < 8; i++)
        #pragma unroll
        for (int j = 0; j < 8; j++) acc[i][j] = 0.f;

    for (int k0 = 0; k0 < D; k0 += 16) {
        #pragma unroll
        for (int i = 0; i < 2; i++) {
            int idx = i * 256 + tid;
            int row = idx >> 2;
            int c4  = idx & 3;
            int gr  = bm + row;
            float4 v = make_float4(0.f, 0.f, 0.f, 0.f);
            if (gr < M) v = *(const float4*)&A[(size_t)gr * D + k0 + c4 * 4];
            As[c4 * 4 + 0][row] = v.x;
            As[c4 * 4 + 1][row] = v.y;
            As[c4 * 4 + 2][row] = v.z;
            As[c4 * 4 + 3][row] = v.w;
        }
        #pragma unroll
        for (int i = 0; i < 2; i++) {
            int idx = i * 256 + tid;
            int r  = idx >> 5;
            int c4 = idx & 31;
            *(float4*)&Bs[r][c4 * 4] =
                *(const float4*)&B[(size_t)(k0 + r) * D + bn + c4 * 4];
        }
        __syncthreads();

        #pragma unroll
        for (int k = 0; k < 16; k++) {
            float a[8], bb[8];
            *(float4*)&a[0]  = *(float4*)&As[k][ty * 8];
            *(float4*)&a[4]  = *(float4*)&As[k][ty * 8 + 4];
            *(float4*)&bb[0] = *(float4*)&Bs[k][tx * 8];
            *(float4*)&bb[4] = *(float4*)&Bs[k][tx * 8 + 4];
            #pragma unroll
            for (int i = 0; i < 8; i++)
                #pragma unroll
                for (int j = 0; j < 8; j++)
                    acc[i][j] = fmaf(a[i], bb[j], acc[i][j]);
        }
        __syncthreads();
    }

    float bv[8];
    #pragma unroll
    for (int j = 0; j < 8; j++) bv[j] = bias[bn + tx * 8 + j];

    #pragma unroll
    for (int i = 0; i < 8; i++) {
        int gr = bm + ty * 8 + i;
        if (gr >= M) continue;
        #pragma unroll
        for (int j = 0; j < 8; j += 4) {
            int gc = bn + tx * 8 + j;
            float4 o;
            o.x = fmaxf(acc[i][j + 0] + bv[j + 0], 0.f);
            o.y = fmaxf(acc[i][j + 1] + bv[j + 1], 0.f);
            o.z = fmaxf(acc[i][j + 2] + bv[j + 2], 0.f);
            o.w = fmaxf(acc[i][j + 3] + bv[j + 3], 0.f);
            *(float4*)&C[(size_t)gr * D + gc] = o;
        }
    }
}

// ---------------------------------------------------------------- launch

extern "C" void kernel_launch(void* const* d_in, const int* in_sizes, int n_in,
                              void* d_out, int out_size) {
    const float* x     = (const float*)d_in[0];
    const void*  src   = d_in[1];
    const void*  dst   = d_in[2];
    const float* gamma = (const float*)d_in[3];
    const float* beta  = (const float*)d_in[4];
    const float* W     = (const float*)d_in[5];
    const float* b     = (const float*)d_in[6];

    int N = in_sizes[0] / D;
    int E = in_sizes[1];
    int L = in_sizes[3] / D;

    // index dtype detection + conversion, then graph structure
    detect_dtype_kernel<<<1, 32>>>((const int*)src);
    convert_idx_kernel<<<(E + 255) / 256, 256>>>(src, dst, E, N);
    init_counts_kernel<<<(N + 255) / 256, 256>>>(N);
    degree_kernel<<<(E + 255) / 256, 256>>>(E);
    norm_kernel<<<(N + 255) / 256, 256>>>(N);
    scan_kernel<<<1, 1024>>>(N);
    csr_fill_kernel<<<(E + 255) / 256, 256>>>(E);

    dim3 gemm_grid((N + 127) / 128, D / 128);

    for (int l = 0; l < L; l++) {
        const float* x_ext = (l == 0) ? x : nullptr;   // nullptr -> g_x
        bn_zero_kernel<<<1, D>>>();
        bn_stats_kernel<<<256, 256>>>(x_ext, N);
        bn_final_kernel<<<1, D>>>(gamma + (size_t)l * D, beta + (size_t)l * D,
                                  1.0f / (float)N);
        normscale_kernel<<<(N * D4 + 255) / 256, 256>>>(x_ext, N);
        aggregate_kernel<<<N, 128>>>(N);
        float* cext = (l == L - 1) ? (float*)d_out : nullptr;  // nullptr -> g_x
        gemm_bias_relu_kernel<<<gemm_grid, 256>>>(
            W + (size_t)l * D * D, b + (size_t)l * D, cext, N);
    }
}

// round 7
// speedup vs baseline: 2.0852x; 2.0852x over previous
#include <cuda_runtime.h>
#include <cuda_bf16.h>
#include <cstdint>

// GCNConv: 3x [BatchNorm -> GraphConv(norm=both) -> ReLU], N=10000 E=160000 D=512
// GEMM via mma.sync bf16 (HMMA) with bf16x3 split emulation of fp32.
// (tcgen05 unavailable: harness builds PTX at .target sm_103, not sm_103a.)
// R6 fix: device-global weight buffers must be resolved in DEVICE code;
// passing g_bhi+off from host passed the host shadow symbol (reads zeros via ATS).

#define D 512
#define D4 128
#define NMAX 10240
#define EMAX 200000

__device__ float g_h[(size_t)NMAX * D];
__device__ float g_x[(size_t)NMAX * D];
__device__ __nv_bfloat16 g_ahi[(size_t)NMAX * D];
__device__ __nv_bfloat16 g_alo[(size_t)NMAX * D];
__device__ __nv_bfloat16 g_bhi[(size_t)3 * D * D];   // transposed: [l][n][k]
__device__ __nv_bfloat16 g_blo[(size_t)3 * D * D];
__device__ float g_srcnorm[NMAX];
__device__ float g_dstnorm[NMAX];
__device__ int   g_src[EMAX];
__device__ int   g_dst[EMAX];
__device__ int   g_outdeg[NMAX];
__device__ int   g_indeg[NMAX];
__device__ int   g_cursor[NMAX];
__device__ int   g_rowoff[NMAX + 1];
__device__ int   g_csr[EMAX];
__device__ float g_colsum[D];
__device__ float g_colsq[D];
__device__ float g_scale[D];
__device__ float g_shift[D];
__device__ int   g_is64;

// ------------------------------------------------------------ ptx helpers

__device__ __forceinline__ uint32_t smem_u32(const void* p) {
    uint32_t a;
    asm("{ .reg .u64 t; cvta.to.shared.u64 t, %1; cvt.u32.u64 %0, t; }"
        : "=r"(a) : "l"(p));
    return a;
}

#define LDSM_X4(r, addr) \
    asm volatile("ldmatrix.sync.aligned.m8n8.x4.shared.b16 {%0,%1,%2,%3}, [%4];" \
        : "=r"((r)[0]), "=r"((r)[1]), "=r"((r)[2]), "=r"((r)[3]) : "r"(addr))
#define LDSM_X2(r, addr) \
    asm volatile("ldmatrix.sync.aligned.m8n8.x2.shared.b16 {%0,%1}, [%2];" \
        : "=r"((r)[0]), "=r"((r)[1]) : "r"(addr))
#define MMA_BF16(d, a, b) \
    asm volatile("mma.sync.aligned.m16n8k16.row.col.f32.bf16.bf16.f32 " \
        "{%0,%1,%2,%3}, {%4,%5,%6,%7}, {%8,%9}, {%0,%1,%2,%3};" \
        : "+f"((d)[0]), "+f"((d)[1]), "+f"((d)[2]), "+f"((d)[3]) \
        : "r"((a)[0]), "r"((a)[1]), "r"((a)[2]), "r"((a)[3]), \
          "r"((b)[0]), "r"((b)[1]))

// ------------------------------------------------------------ dtype handling

__global__ void detect_dtype_kernel(const int* __restrict__ p) {
    if (threadIdx.x == 0) {
        int all0 = 1;
        for (int i = 1; i < 128; i += 2)
            if (p[i] != 0) { all0 = 0; break; }
        g_is64 = all0;
    }
}

__global__ void convert_idx_kernel(const void* __restrict__ srcp,
                                   const void* __restrict__ dstp, int E, int N) {
    int e = blockIdx.x * blockDim.x + threadIdx.x;
    if (e >= E) return;
    int s, d;
    if (g_is64) {
        s = (int)((const long long*)srcp)[e];
        d = (int)((const long long*)dstp)[e];
    } else {
        s = ((const int*)srcp)[e];
        d = ((const int*)dstp)[e];
    }
    s = min(max(s, 0), N - 1);
    d = min(max(d, 0), N - 1);
    g_src[e] = s;
    g_dst[e] = d;
}

// ---------------------------------------------------------------- graph prep

__global__ void init_counts_kernel(int N) {
    int i = blockIdx.x * blockDim.x + threadIdx.x;
    if (i < N) { g_outdeg[i] = 0; g_indeg[i] = 0; g_cursor[i] = 0; }
}

__global__ void degree_kernel(int E) {
    int e = blockIdx.x * blockDim.x + threadIdx.x;
    if (e < E) {
        atomicAdd(&g_outdeg[g_src[e]], 1);
        atomicAdd(&g_indeg[g_dst[e]], 1);
    }
}

__global__ void norm_kernel(int N) {
    int i = blockIdx.x * blockDim.x + threadIdx.x;
    if (i < N) {
        int od = g_outdeg[i]; if (od < 1) od = 1;
        int id = g_indeg[i];  if (id < 1) id = 1;
        g_srcnorm[i] = rsqrtf((float)od);
        g_dstnorm[i] = rsqrtf((float)id);
    }
}

__global__ void scan_kernel(int N) {
    __shared__ int warp_sums[32];
    int tid = threadIdx.x, lane = tid & 31, wid = tid >> 5;
    int chunk = (N + 1023) / 1024;
    int start = tid * chunk;
    int end = start + chunk; if (end > N) end = N;
    int s = 0;
    for (int i = start; i < end; i++) s += g_indeg[i];
    int v = s;
    #pragma unroll
    for (int o = 1; o < 32; o <<= 1) {
        int t = __shfl_up_sync(0xFFFFFFFFu, v, o);
        if (lane >= o) v += t;
    }
    if (lane == 31) warp_sums[wid] = v;
    __syncthreads();
    if (wid == 0) {
        int w = warp_sums[lane];
        #pragma unroll
        for (int o = 1; o < 32; o <<= 1) {
            int t = __shfl_up_sync(0xFFFFFFFFu, w, o);
            if (lane >= o) w += t;
        }
        warp_sums[lane] = w;
    }
    __syncthreads();
    int excl = (v - s) + (wid > 0 ? warp_sums[wid - 1] : 0);
    int run = excl;
    for (int i = start; i < end; i++) { g_rowoff[i] = run; run += g_indeg[i]; }
    if (start < N && end == N) g_rowoff[N] = run;
}

__global__ void csr_fill_kernel(int E) {
    int e = blockIdx.x * blockDim.x + threadIdx.x;
    if (e < E) {
        int d = g_dst[e];
        int p = atomicAdd(&g_cursor[d], 1);
        g_csr[g_rowoff[d] + p] = g_src[e];
    }
}

// ----------------------------------------------------- W transpose + split

__global__ void wsplit_kernel(const float* __restrict__ W) {
    __shared__ float tile[32][33];
    int l = blockIdx.z;
    int kb = blockIdx.x * 32, nb = blockIdx.y * 32;
    int tx = threadIdx.x, ty = threadIdx.y;   // 32 x 8
    const float* Wl = W + (size_t)l * D * D;
    #pragma unroll
    for (int i = 0; i < 32; i += 8)
        tile[ty + i][tx] = Wl[(size_t)(kb + ty + i) * D + nb + tx];
    __syncthreads();
    size_t off = (size_t)l * D * D;
    #pragma unroll
    for (int i = 0; i < 32; i += 8) {
        float v = tile[tx][ty + i];
        __nv_bfloat16 hi = __float2bfloat16(v);
        __nv_bfloat16 lo = __float2bfloat16(v - __bfloat162float(hi));
        size_t idx = off + (size_t)(nb + ty + i) * D + kb + tx;
        g_bhi[idx] = hi;
        g_blo[idx] = lo;
    }
}

// ---------------------------------------------------------------- batch norm

__global__ void bn_zero_kernel() {
    int j = threadIdx.x;
    g_colsum[j] = 0.f;
    g_colsq[j]  = 0.f;
}

__global__ void bn_stats_kernel(const float* __restrict__ x_ext, int N) {
    const float* __restrict__ x = x_ext ? x_ext : g_x;
    int t = threadIdx.x;
    float s0 = 0.f, q0 = 0.f, s1 = 0.f, q1 = 0.f;
    for (int r = blockIdx.x; r < N; r += gridDim.x) {
        float v0 = x[(size_t)r * D + t];
        float v1 = x[(size_t)r * D + t + 256];
        s0 += v0; q0 += v0 * v0;
        s1 += v1; q1 += v1 * v1;
    }
    atomicAdd(&g_colsum[t],       s0);
    atomicAdd(&g_colsq[t],        q0);
    atomicAdd(&g_colsum[t + 256], s1);
    atomicAdd(&g_colsq[t + 256],  q1);
}

__global__ void bn_final_kernel(const float* __restrict__ gamma,
                                const float* __restrict__ beta, float invN) {
    int j = threadIdx.x;
    float mu  = g_colsum[j] * invN;
    float var = g_colsq[j] * invN - mu * mu;
    float rs  = rsqrtf(var + 1e-5f);
    float sc  = rs * gamma[j];
    g_scale[j] = sc;
    g_shift[j] = beta[j] - mu * sc;
}

__global__ void normscale_kernel(const float* __restrict__ x_ext, int N) {
    const float* __restrict__ x = x_ext ? x_ext : g_x;
    int i4 = blockIdx.x * blockDim.x + threadIdx.x;
    if (i4 >= N * D4) return;
    int c4  = i4 & (D4 - 1);
    int row = i4 >> 7;
    float4 v  = ((const float4*)x)[i4];
    float4 sc = ((const float4*)g_scale)[c4];
    float4 sh = ((const float4*)g_shift)[c4];
    float sn  = g_srcnorm[row];
    float4 o;
    o.x = (v.x * sc.x + sh.x) * sn;
    o.y = (v.y * sc.y + sh.y) * sn;
    o.z = (v.z * sc.z + sh.z) * sn;
    o.w = (v.w * sc.w + sh.w) * sn;
    ((float4*)g_h)[i4] = o;
}

// ------------------------------------------- aggregation (emits bf16 hi/lo)

__global__ void aggregate_kernel(int N) {
    int node = blockIdx.x;                 // grid = NPAD (rows >= N are zero)
    int t = threadIdx.x;                   // 128 threads x float4
    __nv_bfloat16 hv[4], lv[4];
    if (node >= N) {
        #pragma unroll
        for (int c = 0; c < 4; c++) { hv[c] = __float2bfloat16(0.f); lv[c] = hv[c]; }
        *(uint2*)&g_ahi[(size_t)node * D + t * 4] = *(uint2*)hv;
        *(uint2*)&g_alo[(size_t)node * D + t * 4] = *(uint2*)lv;
        return;
    }
    int e0 = g_rowoff[node], e1 = g_rowoff[node + 1];
    const float4* __restrict__ h4 = (const float4*)g_h;
    float4 acc = make_float4(0.f, 0.f, 0.f, 0.f);
    int e = e0;
    for (; e + 1 < e1; e += 2) {
        int s0 = g_csr[e], s1 = g_csr[e + 1];
        float4 v0 = h4[(size_t)s0 * D4 + t];
        float4 v1 = h4[(size_t)s1 * D4 + t];
        acc.x += v0.x + v1.x; acc.y += v0.y + v1.y;
        acc.z += v0.z + v1.z; acc.w += v0.w + v1.w;
    }
    if (e < e1) {
        int s = g_csr[e];
        float4 v = h4[(size_t)s * D4 + t];
        acc.x += v.x; acc.y += v.y; acc.z += v.z; acc.w += v.w;
    }
    float dn = g_dstnorm[node];
    float a[4] = {acc.x * dn, acc.y * dn, acc.z * dn, acc.w * dn};
    #pragma unroll
    for (int c = 0; c < 4; c++) {
        hv[c] = __float2bfloat16(a[c]);
        lv[c] = __float2bfloat16(a[c] - __bfloat162float(hv[c]));
    }
    *(uint2*)&g_ahi[(size_t)node * D + t * 4] = *(uint2*)hv;
    *(uint2*)&g_alo[(size_t)node * D + t * 4] = *(uint2*)lv;
}

// ------------------------------------------------ mma.sync GEMM (bf16x3)

// C[m,n] = relu(sum_k A[m,k]*Bt[n,k] + bias[n]);  A=(ahi+alo), Bt=(bhi+blo)
// CTA tile 128x64, BK=32; 8 warps (4m x 2n), warp tile 32x32.
#define BPAD 40   // row stride (bf16) for SMEM tiles; 80B -> ldmatrix conflict-free

__global__ __launch_bounds__(256, 2)
void gemm_mma_kernel(int layer,
                     const float* __restrict__ bias,
                     float* __restrict__ Cext, int M) {
    __shared__ __nv_bfloat16 As_hi[128 * BPAD];
    __shared__ __nv_bfloat16 As_lo[128 * BPAD];
    __shared__ __nv_bfloat16 Bs_hi[64 * BPAD];
    __shared__ __nv_bfloat16 Bs_lo[64 * BPAD];

    // resolve device symbols in DEVICE code (host-side &g_bhi is a shadow!)
    const __nv_bfloat16* __restrict__ Bhi = g_bhi + (size_t)layer * D * D;
    const __nv_bfloat16* __restrict__ Blo = g_blo + (size_t)layer * D * D;

    float* __restrict__ C = Cext ? Cext : g_x;
    int tid = threadIdx.x;
    int lane = tid & 31;
    int wid = tid >> 5;
    int wm = wid & 3;          // 0..3 -> 32-row band
    int wn = wid >> 2;         // 0..1 -> 32-col band
    int m0 = blockIdx.x * 128, n0 = blockIdx.y * 64;

    float acc[2][4][4];
    #pragma unroll
    for (int i = 0; i < 2; i++)
        #pragma unroll
        for (int j = 0; j < 4; j++)
            #pragma unroll
            for (int k = 0; k < 4; k++) acc[i][j][k] = 0.f;

    int a_row = wm * 32 + (lane & 15);
    int a_col = (lane >> 4) * 8;                 // + ks
    int b_row = wn * 32 + (lane & 7);
    int b_col = ((lane >> 3) & 1) * 8;           // + ks

    for (int kc = 0; kc < 16; kc++) {
        int k0 = kc * 32;
        // A tiles: 128 rows x 32 cols (4 x 16B segs/row): 512 segs, 2/thread
        #pragma unroll
        for (int i = 0; i < 2; i++) {
            int idx = i * 256 + tid;
            int row = idx >> 2, seg = idx & 3;
            size_t ga = (size_t)(m0 + row) * D + k0 + seg * 8;
            *(uint4*)&As_hi[row * BPAD + seg * 8] = *(const uint4*)(g_ahi + ga);
            *(uint4*)&As_lo[row * BPAD + seg * 8] = *(const uint4*)(g_alo + ga);
        }
        // B tiles: 64 rows x 32 cols: 256 segs, 1/thread
        {
            int row = tid >> 2, seg = tid & 3;
            size_t gb = (size_t)(n0 + row) * D + k0 + seg * 8;
            *(uint4*)&Bs_hi[row * BPAD + seg * 8] = *(const uint4*)(Bhi + gb);
            *(uint4*)&Bs_lo[row * BPAD + seg * 8] = *(const uint4*)(Blo + gb);
        }
        __syncthreads();

        #pragma unroll
        for (int ks = 0; ks < 32; ks += 16) {
            uint32_t ahi[2][4], alo[2][4], bfr[4][2];
            #pragma unroll
            for (int mi = 0; mi < 2; mi++) {
                uint32_t ad = smem_u32(&As_hi[(a_row + mi * 16) * BPAD + a_col + ks]);
                LDSM_X4(ahi[mi], ad);
                ad = smem_u32(&As_lo[(a_row + mi * 16) * BPAD + a_col + ks]);
                LDSM_X4(alo[mi], ad);
            }
            // B hi: hi*hi and lo*hi
            #pragma unroll
            for (int ni = 0; ni < 4; ni++) {
                uint32_t bd = smem_u32(&Bs_hi[(b_row + ni * 8) * BPAD + b_col + ks]);
                LDSM_X2(bfr[ni], bd);
            }
            #pragma unroll
            for (int mi = 0; mi < 2; mi++)
                #pragma unroll
                for (int ni = 0; ni < 4; ni++) {
                    MMA_BF16(acc[mi][ni], ahi[mi], bfr[ni]);
                    MMA_BF16(acc[mi][ni], alo[mi], bfr[ni]);
                }
            // B lo: hi*lo
            #pragma unroll
            for (int ni = 0; ni < 4; ni++) {
                uint32_t bd = smem_u32(&Bs_lo[(b_row + ni * 8) * BPAD + b_col + ks]);
                LDSM_X2(bfr[ni], bd);
            }
            #pragma unroll
            for (int mi = 0; mi < 2; mi++)
                #pragma unroll
                for (int ni = 0; ni < 4; ni++)
                    MMA_BF16(acc[mi][ni], ahi[mi], bfr[ni]);
        }
        __syncthreads();
    }

    // epilogue: bias + relu, fp32 store
    int rbase = m0 + wm * 32 + (lane >> 2);
    int cbase = n0 + wn * 32 + (lane & 3) * 2;
    #pragma unroll
    for (int ni = 0; ni < 4; ni++) {
        int c = cbase + ni * 8;
        float b0 = bias[c], b1 = bias[c + 1];
        #pragma unroll
        for (int mi = 0; mi < 2; mi++) {
            int r0 = rbase + mi * 16;
            if (r0 < M) {
                float2 o;
                o.x = fmaxf(acc[mi][ni][0] + b0, 0.f);
                o.y = fmaxf(acc[mi][ni][1] + b1, 0.f);
                *(float2*)&C[(size_t)r0 * D + c] = o;
            }
            int r1 = r0 + 8;
            if (r1 < M) {
                float2 o;
                o.x = fmaxf(acc[mi][ni][2] + b0, 0.f);
                o.y = fmaxf(acc[mi][ni][3] + b1, 0.f);
                *(float2*)&C[(size_t)r1 * D + c] = o;
            }
        }
    }
}

// ---------------------------------------------------------------- launch

extern "C" void kernel_launch(void* const* d_in, const int* in_sizes, int n_in,
                              void* d_out, int out_size) {
    const float* x     = (const float*)d_in[0];
    const void*  src   = d_in[1];
    const void*  dst   = d_in[2];
    const float* gamma = (const float*)d_in[3];
    const float* beta  = (const float*)d_in[4];
    const float* W     = (const float*)d_in[5];
    const float* b     = (const float*)d_in[6];

    int N = in_sizes[0] / D;
    int E = in_sizes[1];
    int L = in_sizes[3] / D;
    int NPAD = ((N + 127) / 128) * 128;

    detect_dtype_kernel<<<1, 32>>>((const int*)src);
    convert_idx_kernel<<<(E + 255) / 256, 256>>>(src, dst, E, N);
    init_counts_kernel<<<(N + 255) / 256, 256>>>(N);
    degree_kernel<<<(E + 255) / 256, 256>>>(E);
    norm_kernel<<<(N + 255) / 256, 256>>>(N);
    scan_kernel<<<1, 1024>>>(N);
    csr_fill_kernel<<<(E + 255) / 256, 256>>>(E);
    wsplit_kernel<<<dim3(16, 16, (unsigned)L), dim3(32, 8)>>>(W);

    dim3 gemm_grid(NPAD / 128, D / 64);

    for (int l = 0; l < L; l++) {
        const float* x_ext = (l == 0) ? x : nullptr;   // nullptr -> g_x
        bn_zero_kernel<<<1, D>>>();
        bn_stats_kernel<<<256, 256>>>(x_ext, N);
        bn_final_kernel<<<1, D>>>(gamma + (size_t)l * D, beta + (size_t)l * D,
                                  1.0f / (float)N);
        normscale_kernel<<<(N * D4 + 255) / 256, 256>>>(x_ext, N);
        aggregate_kernel<<<NPAD, 128>>>(N);
        float* cext = (l == L - 1) ? (float*)d_out : nullptr;
        gemm_mma_kernel<<<gemm_grid, 256>>>(l, b + (size_t)l * D, cext, N);
    }
}

// round 8
// speedup vs baseline: 2.1032x; 1.0087x over previous
#include <cuda_runtime.h>
#include <cuda_bf16.h>
#include <cstdint>

// GCNConv: 3x [BatchNorm -> GraphConv(norm=both) -> ReLU], N=10000 E=160000 D=512
// GEMM via mma.sync bf16 (HMMA) with bf16x3 split emulation of fp32.
// R8: normscale fused into aggregation; BN stats fused into GEMM epilogue;
//     cp.async double-buffered GEMM mainloop.

#define D 512
#define D4 128
#define NMAX 10240
#define EMAX 200000
#define BPAD 40   // SMEM row stride (bf16); 80B rows -> ldmatrix conflict-free

__device__ float g_x[(size_t)NMAX * D];
__device__ __nv_bfloat16 g_ahi[(size_t)NMAX * D];
__device__ __nv_bfloat16 g_alo[(size_t)NMAX * D];
__device__ __nv_bfloat16 g_bhi[(size_t)3 * D * D];   // transposed: [l][n][k]
__device__ __nv_bfloat16 g_blo[(size_t)3 * D * D];
__device__ float g_srcnorm[NMAX];
__device__ float g_dstnorm[NMAX];
__device__ int   g_src[EMAX];
__device__ int   g_dst[EMAX];
__device__ int   g_outdeg[NMAX];
__device__ int   g_indeg[NMAX];
__device__ int   g_cursor[NMAX];
__device__ int   g_rowoff[NMAX + 1];
__device__ int   g_csr[EMAX];
__device__ float g_colsum[D];
__device__ float g_colsq[D];
__device__ float g_scale[D];
__device__ float g_shift[D];
__device__ int   g_is64;

// ------------------------------------------------------------ ptx helpers

__device__ __forceinline__ uint32_t smem_u32(const void* p) {
    uint32_t a;
    asm("{ .reg .u64 t; cvta.to.shared.u64 t, %1; cvt.u32.u64 %0, t; }"
        : "=r"(a) : "l"(p));
    return a;
}
#define LDSM_X4(r, addr) \
    asm volatile("ldmatrix.sync.aligned.m8n8.x4.shared.b16 {%0,%1,%2,%3}, [%4];" \
        : "=r"((r)[0]), "=r"((r)[1]), "=r"((r)[2]), "=r"((r)[3]) : "r"(addr))
#define LDSM_X2(r, addr) \
    asm volatile("ldmatrix.sync.aligned.m8n8.x2.shared.b16 {%0,%1}, [%2];" \
        : "=r"((r)[0]), "=r"((r)[1]) : "r"(addr))
#define MMA_BF16(d, a, b) \
    asm volatile("mma.sync.aligned.m16n8k16.row.col.f32.bf16.bf16.f32 " \
        "{%0,%1,%2,%3}, {%4,%5,%6,%7}, {%8,%9}, {%0,%1,%2,%3};" \
        : "+f"((d)[0]), "+f"((d)[1]), "+f"((d)[2]), "+f"((d)[3]) \
        : "r"((a)[0]), "r"((a)[1]), "r"((a)[2]), "r"((a)[3]), \
          "r"((b)[0]), "r"((b)[1]))
#define CP16(saddr, gptr) \
    asm volatile("cp.async.cg.shared.global [%0], [%1], 16;" \
                 :: "r"(saddr), "l"(gptr) : "memory")
#define CP_COMMIT() asm volatile("cp.async.commit_group;" ::: "memory")
#define CP_WAIT(n)  asm volatile("cp.async.wait_group %0;" :: "n"(n) : "memory")

// ------------------------------------------------------------ prep

__global__ void detect_dtype_kernel(const int* __restrict__ p) {
    if (threadIdx.x == 0) {
        int all0 = 1;
        for (int i = 1; i < 128; i += 2)
            if (p[i] != 0) { all0 = 0; break; }
        g_is64 = all0;
    }
}

// zero counters (i<N) + convert/clamp indices (i<E) in one kernel
__global__ void prep_kernel(const void* __restrict__ srcp,
                            const void* __restrict__ dstp, int E, int N) {
    int e = blockIdx.x * blockDim.x + threadIdx.x;
    if (e < N) { g_outdeg[e] = 0; g_indeg[e] = 0; g_cursor[e] = 0; }
    if (e >= E) return;
    int s, d;
    if (g_is64) {
        s = (int)((const long long*)srcp)[e];
        d = (int)((const long long*)dstp)[e];
    } else {
        s = ((const int*)srcp)[e];
        d = ((const int*)dstp)[e];
    }
    s = min(max(s, 0), N - 1);
    d = min(max(d, 0), N - 1);
    g_src[e] = s;
    g_dst[e] = d;
}

__global__ void degree_kernel(int E) {
    int e = blockIdx.x * blockDim.x + threadIdx.x;
    if (e < E) {
        atomicAdd(&g_outdeg[g_src[e]], 1);
        atomicAdd(&g_indeg[g_dst[e]], 1);
    }
}

__global__ void norm_kernel(int N) {
    int i = blockIdx.x * blockDim.x + threadIdx.x;
    if (i < N) {
        int od = g_outdeg[i]; if (od < 1) od = 1;
        int id = g_indeg[i];  if (id < 1) id = 1;
        g_srcnorm[i] = rsqrtf((float)od);
        g_dstnorm[i] = rsqrtf((float)id);
    }
}

__global__ void scan_kernel(int N) {
    __shared__ int warp_sums[32];
    int tid = threadIdx.x, lane = tid & 31, wid = tid >> 5;
    int chunk = (N + 1023) / 1024;
    int start = tid * chunk;
    int end = start + chunk; if (end > N) end = N;
    int s = 0;
    for (int i = start; i < end; i++) s += g_indeg[i];
    int v = s;
    #pragma unroll
    for (int o = 1; o < 32; o <<= 1) {
        int t = __shfl_up_sync(0xFFFFFFFFu, v, o);
        if (lane >= o) v += t;
    }
    if (lane == 31) warp_sums[wid] = v;
    __syncthreads();
    if (wid == 0) {
        int w = warp_sums[lane];
        #pragma unroll
        for (int o = 1; o < 32; o <<= 1) {
            int t = __shfl_up_sync(0xFFFFFFFFu, w, o);
            if (lane >= o) w += t;
        }
        warp_sums[lane] = w;
    }
    __syncthreads();
    int excl = (v - s) + (wid > 0 ? warp_sums[wid - 1] : 0);
    int run = excl;
    for (int i = start; i < end; i++) { g_rowoff[i] = run; run += g_indeg[i]; }
    if (start < N && end == N) g_rowoff[N] = run;
}

__global__ void csr_fill_kernel(int E) {
    int e = blockIdx.x * blockDim.x + threadIdx.x;
    if (e < E) {
        int d = g_dst[e];
        int p = atomicAdd(&g_cursor[d], 1);
        g_csr[g_rowoff[d] + p] = g_src[e];
    }
}

// ----------------------------------------------------- W transpose + split

__global__ void wsplit_kernel(const float* __restrict__ W) {
    __shared__ float tile[32][33];
    int l = blockIdx.z;
    int kb = blockIdx.x * 32, nb = blockIdx.y * 32;
    int tx = threadIdx.x, ty = threadIdx.y;   // 32 x 8
    const float* Wl = W + (size_t)l * D * D;
    #pragma unroll
    for (int i = 0; i < 32; i += 8)
        tile[ty + i][tx] = Wl[(size_t)(kb + ty + i) * D + nb + tx];
    __syncthreads();
    size_t off = (size_t)l * D * D;
    #pragma unroll
    for (int i = 0; i < 32; i += 8) {
        float v = tile[tx][ty + i];
        __nv_bfloat16 hi = __float2bfloat16(v);
        __nv_bfloat16 lo = __float2bfloat16(v - __bfloat162float(hi));
        size_t idx = off + (size_t)(nb + ty + i) * D + kb + tx;
        g_bhi[idx] = hi;
        g_blo[idx] = lo;
    }
}

// ---------------------------------------------------------------- batch norm

__global__ void bn_zero_kernel() {
    int j = threadIdx.x;
    g_colsum[j] = 0.f;
    g_colsq[j]  = 0.f;
}

// layer-0 only: stats over external input x
__global__ void bn_stats_kernel(const float* __restrict__ x, int N) {
    int t = threadIdx.x;
    float s0 = 0.f, q0 = 0.f, s1 = 0.f, q1 = 0.f;
    for (int r = blockIdx.x; r < N; r += gridDim.x) {
        float v0 = x[(size_t)r * D + t];
        float v1 = x[(size_t)r * D + t + 256];
        s0 += v0; q0 += v0 * v0;
        s1 += v1; q1 += v1 * v1;
    }
    atomicAdd(&g_colsum[t],       s0);
    atomicAdd(&g_colsq[t],        q0);
    atomicAdd(&g_colsum[t + 256], s1);
    atomicAdd(&g_colsq[t + 256],  q1);
}

__global__ void bn_final_kernel(const float* __restrict__ gamma,
                                const float* __restrict__ beta, float invN) {
    int j = threadIdx.x;
    float mu  = g_colsum[j] * invN;
    float var = g_colsq[j] * invN - mu * mu;
    float rs  = rsqrtf(var + 1e-5f);
    float sc  = rs * gamma[j];
    g_scale[j] = sc;
    g_shift[j] = beta[j] - mu * sc;
}

// ---------------------- aggregation (BN-normalize fused, emits bf16 hi/lo)

__global__ void aggregate_kernel(const float* __restrict__ x_ext, int N) {
    int node = blockIdx.x;                 // grid = NPAD (rows >= N are zero)
    int t = threadIdx.x;                   // 128 threads x float4

    // block 0 zeroes the stats accumulators for the NEXT layer's stats
    // (safe: bn_final already consumed them; gemm fills them after this kernel)
    if (node == 0) {
        #pragma unroll
        for (int j = t; j < D; j += 128) { g_colsum[j] = 0.f; g_colsq[j] = 0.f; }
    }

    __nv_bfloat16 hv[4], lv[4];
    if (node >= N) {
        #pragma unroll
        for (int c = 0; c < 4; c++) { hv[c] = __float2bfloat16(0.f); lv[c] = hv[c]; }
        *(uint2*)&g_ahi[(size_t)node * D + t * 4] = *(uint2*)hv;
        *(uint2*)&g_alo[(size_t)node * D + t * 4] = *(uint2*)lv;
        return;
    }
    const float4* __restrict__ x4 =
        (const float4*)(x_ext ? x_ext : (const float*)g_x);
    float4 sc = ((const float4*)g_scale)[t];
    float4 sh = ((const float4*)g_shift)[t];

    int e0 = g_rowoff[node], e1 = g_rowoff[node + 1];
    float4 acc = make_float4(0.f, 0.f, 0.f, 0.f);
    for (int e = e0; e < e1; e++) {
        int s = g_csr[e];
        float sn = __ldg(&g_srcnorm[s]);
        float4 v = x4[(size_t)s * D4 + t];
        acc.x += (v.x * sc.x + sh.x) * sn;
        acc.y += (v.y * sc.y + sh.y) * sn;
        acc.z += (v.z * sc.z + sh.z) * sn;
        acc.w += (v.w * sc.w + sh.w) * sn;
    }
    float dn = g_dstnorm[node];
    float a[4] = {acc.x * dn, acc.y * dn, acc.z * dn, acc.w * dn};
    #pragma unroll
    for (int c = 0; c < 4; c++) {
        hv[c] = __float2bfloat16(a[c]);
        lv[c] = __float2bfloat16(a[c] - __bfloat162float(hv[c]));
    }
    *(uint2*)&g_ahi[(size_t)node * D + t * 4] = *(uint2*)hv;
    *(uint2*)&g_alo[(size_t)node * D + t * 4] = *(uint2*)lv;
}

// ------------------------------------------------ mma.sync GEMM (bf16x3)

// C = relu(A @ Bt^T + bias); CTA tile 128x64, BK=32, 2-stage cp.async pipe.
// Epilogue also accumulates per-column sum/sumsq (next layer's BN stats).
#define A_ST  (128 * BPAD)       // elements per A stage
#define B_ST  (64 * BPAD)
#define SM_ELEMS (2 * A_ST * 2 + 2 * B_ST * 2)
#define SM_BYTES (SM_ELEMS * 2)  // 61440

__global__ __launch_bounds__(256, 2)
void gemm_mma_kernel(int layer, const float* __restrict__ bias,
                     float* __restrict__ Cext, int M, int do_stats) {
    extern __shared__ char smraw[];
    __nv_bfloat16* As_hi = (__nv_bfloat16*)smraw;          // [2][A_ST]
    __nv_bfloat16* As_lo = As_hi + 2 * A_ST;
    __nv_bfloat16* Bs_hi = As_lo + 2 * A_ST;               // [2][B_ST]
    __nv_bfloat16* Bs_lo = Bs_hi + 2 * B_ST;

    const __nv_bfloat16* __restrict__ Bhi = g_bhi + (size_t)layer * D * D;
    const __nv_bfloat16* __restrict__ Blo = g_blo + (size_t)layer * D * D;
    float* __restrict__ C = Cext ? Cext : g_x;

    int tid = threadIdx.x;
    int lane = tid & 31;
    int wid = tid >> 5;
    int wm = wid & 3;
    int wn = wid >> 2;
    int m0 = blockIdx.x * 128, n0 = blockIdx.y * 64;

    float acc[2][4][4];
    #pragma unroll
    for (int i = 0; i < 2; i++)
        #pragma unroll
        for (int j = 0; j < 4; j++)
            #pragma unroll
            for (int k = 0; k < 4; k++) acc[i][j][k] = 0.f;

    int a_row = wm * 32 + (lane & 15);
    int a_col = (lane >> 4) * 8;
    int b_row = wn * 32 + (lane & 7);
    int b_col = ((lane >> 3) & 1) * 8;

    // per-thread load coords
    int la_row = tid >> 2, la_seg = tid & 3;       // +64 rows for second half
    int lb_row = tid >> 2, lb_seg = tid & 3;

    #define ISSUE_LOADS(kc, buf) do {                                           \
        int _k0 = (kc) * 32;                                                    \
        int _ab = (buf) * A_ST, _bb = (buf) * B_ST;                             \
        _Pragma("unroll")                                                       \
        for (int _i = 0; _i < 2; _i++) {                                        \
            int _row = la_row + _i * 64;                                        \
            size_t _ga = (size_t)(m0 + _row) * D + _k0 + la_seg * 8;            \
            uint32_t _sa = smem_u32(&As_hi[_ab + _row * BPAD + la_seg * 8]);    \
            CP16(_sa, g_ahi + _ga);                                             \
            _sa = smem_u32(&As_lo[_ab + _row * BPAD + la_seg * 8]);             \
            CP16(_sa, g_alo + _ga);                                             \
        }                                                                       \
        {                                                                       \
            size_t _gb = (size_t)(n0 + lb_row) * D + _k0 + lb_seg * 8;          \
            uint32_t _sb = smem_u32(&Bs_hi[_bb + lb_row * BPAD + lb_seg * 8]);  \
            CP16(_sb, Bhi + _gb);                                               \
            _sb = smem_u32(&Bs_lo[_bb + lb_row * BPAD + lb_seg * 8]);           \
            CP16(_sb, Blo + _gb);                                               \
        }                                                                       \
        CP_COMMIT();                                                            \
    } while (0)

    ISSUE_LOADS(0, 0);

    for (int kc = 0; kc < 16; kc++) {
        if (kc < 15) { ISSUE_LOADS(kc + 1, (kc + 1) & 1); CP_WAIT(1); }
        else         { CP_WAIT(0); }
        __syncthreads();

        int ab = (kc & 1) * A_ST, bb = (kc & 1) * B_ST;
        #pragma unroll
        for (int ks = 0; ks < 32; ks += 16) {
            uint32_t ahi[2][4], alo[2][4], bfr[4][2];
            #pragma unroll
            for (int mi = 0; mi < 2; mi++) {
                uint32_t ad = smem_u32(&As_hi[ab + (a_row + mi * 16) * BPAD + a_col + ks]);
                LDSM_X4(ahi[mi], ad);
                ad = smem_u32(&As_lo[ab + (a_row + mi * 16) * BPAD + a_col + ks]);
                LDSM_X4(alo[mi], ad);
            }
            #pragma unroll
            for (int ni = 0; ni < 4; ni++) {
                uint32_t bd = smem_u32(&Bs_hi[bb + (b_row + ni * 8) * BPAD + b_col + ks]);
                LDSM_X2(bfr[ni], bd);
            }
            #pragma unroll
            for (int mi = 0; mi < 2; mi++)
                #pragma unroll
                for (int ni = 0; ni < 4; ni++) {
                    MMA_BF16(acc[mi][ni], ahi[mi], bfr[ni]);
                    MMA_BF16(acc[mi][ni], alo[mi], bfr[ni]);
                }
            #pragma unroll
            for (int ni = 0; ni < 4; ni++) {
                uint32_t bd = smem_u32(&Bs_lo[bb + (b_row + ni * 8) * BPAD + b_col + ks]);
                LDSM_X2(bfr[ni], bd);
            }
            #pragma unroll
            for (int mi = 0; mi < 2; mi++)
                #pragma unroll
                for (int ni = 0; ni < 4; ni++)
                    MMA_BF16(acc[mi][ni], ahi[mi], bfr[ni]);
        }
        __syncthreads();
    }

    // epilogue: bias + relu + store; optionally accumulate BN stats in smem
    float* cs = (float*)smraw;          // pipeline done; reuse smem
    float* cq = cs + 64;
    if (do_stats) {
        if (tid < 64) { cs[tid] = 0.f; cq[tid] = 0.f; }
        __syncthreads();
    }

    int rbase = m0 + wm * 32 + (lane >> 2);
    int lcb   = wn * 32 + (lane & 3) * 2;
    #pragma unroll
    for (int ni = 0; ni < 4; ni++) {
        int lc = lcb + ni * 8;
        int c  = n0 + lc;
        float b0 = bias[c], b1 = bias[c + 1];
        float sx = 0.f, sy = 0.f, qx = 0.f, qy = 0.f;
        #pragma unroll
        for (int mi = 0; mi < 2; mi++) {
            int r0 = rbase + mi * 16;
            if (r0 < M) {
                float2 o;
                o.x = fmaxf(acc[mi][ni][0] + b0, 0.f);
                o.y = fmaxf(acc[mi][ni][1] + b1, 0.f);
                *(float2*)&C[(size_t)r0 * D + c] = o;
                sx += o.x; qx += o.x * o.x;
                sy += o.y; qy += o.y * o.y;
            }
            int r1 = r0 + 8;
            if (r1 < M) {
                float2 o;
                o.x = fmaxf(acc[mi][ni][2] + b0, 0.f);
                o.y = fmaxf(acc[mi][ni][3] + b1, 0.f);
                *(float2*)&C[(size_t)r1 * D + c] = o;
                sx += o.x; qx += o.x * o.x;
                sy += o.y; qy += o.y * o.y;
            }
        }
        if (do_stats) {
            atomicAdd(&cs[lc], sx);     atomicAdd(&cq[lc], qx);
            atomicAdd(&cs[lc + 1], sy); atomicAdd(&cq[lc + 1], qy);
        }
    }
    if (do_stats) {
        __syncthreads();
        if (tid < 64) {
            atomicAdd(&g_colsum[n0 + tid], cs[tid]);
            atomicAdd(&g_colsq[n0 + tid],  cq[tid]);
        }
    }
}

// ---------------------------------------------------------------- launch

extern "C" void kernel_launch(void* const* d_in, const int* in_sizes, int n_in,
                              void* d_out, int out_size) {
    const float* x     = (const float*)d_in[0];
    const void*  src   = d_in[1];
    const void*  dst   = d_in[2];
    const float* gamma = (const float*)d_in[3];
    const float* beta  = (const float*)d_in[4];
    const float* W     = (const float*)d_in[5];
    const float* b     = (const float*)d_in[6];

    int N = in_sizes[0] / D;
    int E = in_sizes[1];
    int L = in_sizes[3] / D;
    int NPAD = ((N + 127) / 128) * 128;

    cudaFuncSetAttribute(gemm_mma_kernel,
                         cudaFuncAttributeMaxDynamicSharedMemorySize, SM_BYTES);

    detect_dtype_kernel<<<1, 32>>>((const int*)src);
    prep_kernel<<<(E + 255) / 256, 256>>>(src, dst, E, N);
    degree_kernel<<<(E + 255) / 256, 256>>>(E);
    norm_kernel<<<(N + 255) / 256, 256>>>(N);
    scan_kernel<<<1, 1024>>>(N);
    csr_fill_kernel<<<(E + 255) / 256, 256>>>(E);
    wsplit_kernel<<<dim3(16, 16, (unsigned)L), dim3(32, 8)>>>(W);

    // layer-0 stats on the external input
    bn_zero_kernel<<<1, D>>>();
    bn_stats_kernel<<<256, 256>>>(x, N);

    dim3 gemm_grid(NPAD / 128, D / 64);

    for (int l = 0; l < L; l++) {
        bn_final_kernel<<<1, D>>>(gamma + (size_t)l * D, beta + (size_t)l * D,
                                  1.0f / (float)N);
        aggregate_kernel<<<NPAD, 128>>>((l == 0) ? x : nullptr, N);
        float* cext = (l == L - 1) ? (float*)d_out : nullptr;
        int do_stats = (l < L - 1) ? 1 : 0;
        gemm_mma_kernel<<<gemm_grid, 256, SM_BYTES>>>(
            l, b + (size_t)l * D, cext, N, do_stats);
    }
}